// round 15
// baseline (speedup 1.0000x reference)
#include <cuda_runtime.h>
#include <cuda_fp16.h>
#include <cstdint>
#include <cstddef>

// ============================================================================
// KAN layer == fp16 GEMM with 2:4 SPARSE spline block:
//   out[2048,1024] = A[2048,9216] @ Bm[1024,9216]^T
// R14: 64x64 warp tiles (halves LDSM bytes/FLOP — R13 proved we sit on the
// shared-memory crossbar floor at 32x32). CTA tile 256x128, 8 warps (4m x 2n),
// 1 CTA/SM with 256-reg budget (acc=128 regs). K-split x2 -> grid (8,8,2)=128
// CTAs; partial sums combined by a small add kernel (deterministic).
// ============================================================================

namespace {
constexpr int B_DIM  = 2048;
constexpr int I_DIM  = 1024;
constexpr int O_DIM  = 1024;
constexpr int MT     = 8;                  // 2048 / 256
constexpr int NT     = 8;                  // 1024 / 128
constexpr int STAGES = 3;
constexpr int KSPLIT = 2;
constexpr int STEPS_PER_KT = 40;           // 80 total (16 dense + 64 sparse)
constexpr int NWARP  = 8;
constexpr int A_CH_HALVES = 256 * 64;      // A chunk: 256 rows x 64 fp16 = 32KB
constexpr int A_CH_BYTES  = A_CH_HALVES * 2;
constexpr int B_CH_HALVES = 128 * 64;      // B chunk: 128 rows x 64 fp16 = 16KB
constexpr int B_CH_BYTES  = B_CH_HALVES * 2;
constexpr int A_CHUNKS    = 80;            // 16 base + 64 compressed spline
constexpr int B_CHUNKS    = 144;           // 16 base + 128 dense spline
constexpr int STAGE_BYTES = A_CH_BYTES + 2 * B_CH_BYTES;   // 64KB
constexpr int SMEM_TOTAL  = 2048 + STAGES * STAGE_BYTES;   // 198656
}  // namespace

// Scratch (__device__ globals; no cudaMalloc allowed).
__device__ __half   g_A   [(size_t)MT * A_CHUNKS * A_CH_HALVES];   // 21 MB
__device__ __half   g_Bm  [(size_t)NT * B_CHUNKS * B_CH_HALVES];   // 18.9 MB
__device__ uint32_t g_meta[(size_t)128 * 256 * 16];                // 2 MB
__device__ float    g_part[(size_t)KSPLIT * B_DIM * O_DIM];        // 16 MB

// ---------------------------------------------------------------- helpers --
__device__ __forceinline__ uint32_t smem_u32(const void* p) {
    uint32_t a;
    asm("{ .reg .u64 t; cvta.to.shared.u64 t, %1; cvt.u32.u64 %0, t; }"
        : "=r"(a) : "l"(p));
    return a;
}
__device__ __forceinline__ uint32_t sw128(uint32_t off) {   // Swizzle<3,4,3>
    return off ^ ((off >> 3) & 0x70);
}
__device__ __forceinline__ void mbar_init(uint32_t m, uint32_t cnt) {
    asm volatile("mbarrier.init.shared.b64 [%0], %1;" :: "r"(m), "r"(cnt) : "memory");
}
__device__ __forceinline__ void mbar_expect_tx(uint32_t m, uint32_t bytes) {
    asm volatile("mbarrier.arrive.expect_tx.shared.b64 _, [%0], %1;"
                 :: "r"(m), "r"(bytes) : "memory");
}
__device__ __forceinline__ void mbar_arrive(uint32_t m) {
    asm volatile("mbarrier.arrive.shared.b64 _, [%0];" :: "r"(m) : "memory");
}
__device__ __forceinline__ void mbar_wait(uint32_t m, uint32_t parity) {
    asm volatile(
        "{\n\t.reg .pred P;\n\t"
        "W%=:\n\t"
        "mbarrier.try_wait.parity.acquire.cta.shared::cta.b64 P, [%0], %1, 0x989680;\n\t"
        "@P bra.uni D%=;\n\t"
        "bra.uni W%=;\n\t"
        "D%=:\n\t}"
        :: "r"(m), "r"(parity) : "memory");
}
__device__ __forceinline__ void mbar_wait_relaxed(uint32_t m, uint32_t parity) {
    asm volatile(
        "{\n\t.reg .pred P;\n\t"
        "W%=:\n\t"
        "mbarrier.try_wait.parity.relaxed.cta.shared::cta.b64 P, [%0], %1, 0x989680;\n\t"
        "@P bra.uni D%=;\n\t"
        "bra.uni W%=;\n\t"
        "D%=:\n\t}"
        :: "r"(m), "r"(parity) : "memory");
}
__device__ __forceinline__ void bulk_g2s(uint32_t dst, const void* src,
                                         uint32_t bytes, uint32_t mbar) {
    asm volatile(
        "cp.async.bulk.shared::cluster.global.mbarrier::complete_tx::bytes "
        "[%0], [%1], %2, [%3];"
        :: "r"(dst), "l"(src), "r"(bytes), "r"(mbar) : "memory");
}
__device__ __forceinline__ void mma_f16(float& c0, float& c1, float& c2, float& c3,
                                        uint32_t a0, uint32_t a1, uint32_t a2,
                                        uint32_t a3, uint32_t b0, uint32_t b1) {
    asm volatile(
        "mma.sync.aligned.m16n8k16.row.col.f32.f16.f16.f32 "
        "{%0,%1,%2,%3}, {%4,%5,%6,%7}, {%8,%9}, {%0,%1,%2,%3};"
        : "+f"(c0), "+f"(c1), "+f"(c2), "+f"(c3)
        : "r"(a0), "r"(a1), "r"(a2), "r"(a3), "r"(b0), "r"(b1));
}
__device__ __forceinline__ void mma_sp(float& c0, float& c1, float& c2, float& c3,
                                       uint32_t a0, uint32_t a1, uint32_t a2,
                                       uint32_t a3, uint32_t b0, uint32_t b1,
                                       uint32_t b2, uint32_t b3, uint32_t e) {
    asm volatile(
        "mma.sp::ordered_metadata.sync.aligned.m16n8k32.row.col.f32.f16.f16.f32 "
        "{%0,%1,%2,%3}, {%4,%5,%6,%7}, {%8,%9,%10,%11}, {%0,%1,%2,%3}, %12, 0x0;"
        : "+f"(c0), "+f"(c1), "+f"(c2), "+f"(c3)
        : "r"(a0), "r"(a1), "r"(a2), "r"(a3),
          "r"(b0), "r"(b1), "r"(b2), "r"(b3), "r"(e));
}
__device__ __forceinline__ void ldm_x4(uint32_t* r, uint32_t addr) {
    asm volatile(
        "ldmatrix.sync.aligned.m8n8.x4.shared.b16 {%0,%1,%2,%3}, [%4];"
        : "=r"(r[0]), "=r"(r[1]), "=r"(r[2]), "=r"(r[3]) : "r"(addr));
}
__device__ __forceinline__ uint32_t h2u(__half2 h) {
    return *reinterpret_cast<uint32_t*>(&h);
}
// reference bucketize: grid knots exact 0.25 multiples; bin clamps to 7
__device__ __forceinline__ int bin_of(float x, float& w) {
    const float xc = fminf(1.0f, fmaxf(-1.0f, x));
    const int gi = (xc >= -0.75f) + (xc >= -0.5f) + (xc >= -0.25f) + (xc >= 0.0f) +
                   (xc >=  0.25f) + (xc >=  0.5f) + (xc >=  0.75f);
    w = (xc - (-1.0f + 0.25f * (float)gi)) * 4.0f;
    return gi;
}
__device__ __forceinline__ uint32_t meta_byte(float x) {
    float w; const int gi = bin_of(x, w);
    const int grp = gi >> 2, p = gi & 3;
    const uint32_t n0 = 0xCu | ((grp == 0 && p < 3) ? (uint32_t)p : 0u);
    const uint32_t n1 = 0xCu | ((grp == 1 && p < 3) ? (uint32_t)p : 0u);
    return n0 | (n1 << 4);
}

// ------------------------------------------------------------ B builder ----
// 128-row n-tiles: [o>>7][k-chunk][sw128((o&127)*128 + group*16)]
__global__ void build_B(const float* __restrict__ W, const float* __restrict__ C) {
    const int o  = blockIdx.y;
    const int kg = blockIdx.x * 128 + threadIdx.x;   // 0..1151 (8-half groups)
    float4 v0, v1;
    if (blockIdx.x == 0) {
        const float4* p = reinterpret_cast<const float4*>(W + (size_t)o * I_DIM + kg * 8);
        v0 = p[0]; v1 = p[1];
    } else {
        const float4* p = reinterpret_cast<const float4*>(C + (size_t)o * 8192 + (kg * 8 - 1024));
        v0 = p[0]; v1 = p[1];
        v0.x *= 0.1f; v0.y *= 0.1f; v0.z *= 0.1f; v0.w *= 0.1f;
        v1.x *= 0.1f; v1.y *= 0.1f; v1.z *= 0.1f; v1.w *= 0.1f;
    }
    uint4 u;
    u.x = h2u(__floats2half2_rn(v0.x, v0.y));
    u.y = h2u(__floats2half2_rn(v0.z, v0.w));
    u.z = h2u(__floats2half2_rn(v1.x, v1.y));
    u.w = h2u(__floats2half2_rn(v1.z, v1.w));
    const int ntile = o >> 7, r = o & 127, ch = kg >> 3;
    char* cb = (char*)(g_Bm + ((size_t)ntile * B_CHUNKS + ch) * B_CH_HALVES);
    *reinterpret_cast<uint4*>(cb + sw128((uint32_t)(r * 128 + (kg & 7) * 16))) = u;
}

// ------------------------------------------------------------ A builder ----
// 256-row m-tiles.
__global__ void build_A(const float* __restrict__ X) {
    const int idx = blockIdx.x * blockDim.x + threadIdx.x;
    if (idx >= B_DIM * I_DIM) return;
    const int b = idx >> 10, i = idx & 1023;
    const float x = X[idx];
    const int mtile = b >> 8, r = b & 255;
    char* tb = (char*)(g_A + (size_t)mtile * A_CHUNKS * A_CH_HALVES);

    {   // base: chunk i>>6, half col i&63
        const int ch = i >> 6;
        const uint32_t off = sw128((uint32_t)(r * 128 + (i & 63) * 2));
        *reinterpret_cast<__half*>(tb + (size_t)ch * A_CH_BYTES + off) =
            __float2half_rn(x);
    }

    float w; const int gi = bin_of(x, w);
    const int slot = (gi >> 2) * 2 + ((gi & 3) == 3 ? 1 : 0);
    const uint32_t w16 = (uint32_t)__half_as_ushort(__float2half_rn(w));
    uint2 u;
    u.x = (slot < 2) ? (w16 << (slot * 16)) : 0u;
    u.y = (slot >= 2) ? (w16 << ((slot - 2) * 16)) : 0u;

    const int ch = 16 + (i >> 4);
    const uint32_t off = sw128((uint32_t)(r * 128 + (i & 15) * 8));
    *reinterpret_cast<uint2*>(tb + (size_t)ch * A_CH_BYTES + off) = u;
}

// --------------------------------------------------------- meta builder ----
// [global 16-row slab 0..127][k32g 0..255][lane-entry 0..15]
__global__ void build_meta(const float* __restrict__ X) {
    extern __shared__ float xs[];            // 16 rows x 1024
    const int blk = blockIdx.x;              // global slab
    const int rowbase = blk * 16;
    for (int v = threadIdx.x; v < 16 * 1024; v += 256)
        xs[v] = X[(size_t)(rowbase + (v >> 10)) * I_DIM + (v & 1023)];
    __syncthreads();
    for (int e = threadIdx.x; e < 4096; e += 256) {
        const int k32g = e >> 4, q = (e >> 1) & 7, t = e & 1;
        const int i0 = k32g * 4 + 2 * t;
        const float* r0 = xs + q * 1024;
        const float* r1 = xs + (q + 8) * 1024;
        const uint32_t lo = meta_byte(r0[i0]) | (meta_byte(r0[i0 + 1]) << 8);
        const uint32_t hi = meta_byte(r1[i0]) | (meta_byte(r1[i0 + 1]) << 8);
        g_meta[(size_t)blk * 4096 + e] = lo | (hi << 16);
    }
}

// ---------------------------------------------------------------- GEMM -----
// grid (8,8,2): mt, nt, kt. 256 threads = 8 warps as 4(m) x 2(n);
// warp tile 64m x 64n. Each kt computes 40 of 80 steps into g_part[kt].
__global__ void __launch_bounds__(256, 1) kan_gemm() {
    extern __shared__ char smem[];
    const uint32_t sbase = smem_u32(smem);
    const uint32_t hdr   = sbase;
    const uint32_t tiles = (sbase + 2047u) & ~1023u;
    const uint32_t mb_full  = hdr;           // 3 x 8B
    const uint32_t mb_empty = hdr + 64;      // 3 x 8B

    const int tid  = threadIdx.x;
    const int wid  = tid >> 5;
    const int lane = tid & 31;
    const int wm = wid & 3;                  // m-slab 0..3 (64 rows each)
    const int wn = wid >> 2;                 // n-slab 0..1 (64 cols each)
    const int mt = blockIdx.x, nt = blockIdx.y, kt = blockIdx.z;
    const int g0 = kt * STEPS_PER_KT;

    if (tid == 0) {
        #pragma unroll
        for (int s = 0; s < STAGES; s++) {
            mbar_init(mb_full  + 8 * s, 1);
            mbar_init(mb_empty + 8 * s, NWARP);
        }
    }
    __syncthreads();

    const __half* gA = g_A  + (size_t)mt * A_CHUNKS * A_CH_HALVES;
    const __half* gB = g_Bm + (size_t)nt * B_CHUNKS * B_CH_HALVES;

    auto produce = [&](int g, int ps) {      // g = global step index
        const uint32_t dst = tiles + (uint32_t)ps * STAGE_BYTES;
        if (g < 16) {
            mbar_expect_tx(mb_full + 8 * ps, A_CH_BYTES + B_CH_BYTES);
            bulk_g2s(dst, gA + (size_t)g * A_CH_HALVES,
                     A_CH_BYTES, mb_full + 8 * ps);
            bulk_g2s(dst + A_CH_BYTES, gB + (size_t)g * B_CH_HALVES,
                     B_CH_BYTES, mb_full + 8 * ps);
        } else {
            mbar_expect_tx(mb_full + 8 * ps, A_CH_BYTES + 2 * B_CH_BYTES);
            bulk_g2s(dst, gA + (size_t)g * A_CH_HALVES,
                     A_CH_BYTES, mb_full + 8 * ps);
            bulk_g2s(dst + A_CH_BYTES,
                     gB + (size_t)(2 * g - 16) * B_CH_HALVES,
                     2 * B_CH_BYTES, mb_full + 8 * ps);
        }
    };

    if (tid == 0) {
        produce(g0 + 0, 0);
        produce(g0 + 1, 1);
    }
    int pcc = STAGES - 1, ps = STAGES - 1, pr = 0;

    float acc[4][8][4];                      // [mi][ni][frag]
    #pragma unroll
    for (int mi = 0; mi < 4; mi++)
        #pragma unroll
        for (int ni = 0; ni < 8; ni++)
            #pragma unroll
            for (int q = 0; q < 4; q++) acc[mi][ni][q] = 0.0f;

    // ldmatrix geometry (SW128, row fixed per lane)
    const uint32_t pat   = (uint32_t)(lane & 7) << 4;
    const uint32_t a_k16 = (uint32_t)((lane >> 4) & 1) << 4;
    const uint32_t b_k16 = (uint32_t)((lane >> 3) & 1) << 4;
    const int a_row_l = ((lane >> 3) & 1) * 8 + (lane & 7);
    const int b_col_l = ((lane >> 4) & 1) * 8 + (lane & 7);
    const uint32_t mlane = (uint32_t)(((lane >> 2) << 1) | (lane & 1));
    const size_t meta_base = ((size_t)(mt * 16 + wm * 4)) * 4096;  // +mi*4096

    int cs = 0, cph = 0;                     // consumer cursor

    for (int ns = 0; ns < STEPS_PER_KT; ns++) {
        const int g = g0 + ns;

        if (tid == 0 && pcc < STEPS_PER_KT) {
            if (pr > 0) mbar_wait_relaxed(mb_empty + 8 * ps, (pr - 1) & 1);
            produce(g0 + pcc, ps);
            pcc++;
            if (++ps == STAGES) { ps = 0; pr++; }
        }

        // metadata prefetch before the stage wait (stage-independent GMEM)
        uint32_t e[4][4];                    // [j][mi]
        if (g >= 16) {
            const int m = g - 16;
            #pragma unroll
            for (int j = 0; j < 4; j++)
                #pragma unroll
                for (int mi = 0; mi < 4; mi++)
                    e[j][mi] = g_meta[meta_base + (size_t)mi * 4096 +
                                      (size_t)(m * 4 + j) * 16 + mlane];
        }

        mbar_wait(mb_full + 8 * cs, cph);

        const uint32_t As_u = tiles + (uint32_t)cs * STAGE_BYTES;
        const uint32_t Bs_u = As_u + A_CH_BYTES;

        uint32_t abase[4];
        #pragma unroll
        for (int mi = 0; mi < 4; mi++)
            abase[mi] = As_u + (uint32_t)(wm * 64 + mi * 16 + a_row_l) * 128;

        if (g < 16) {
            // ---------------- dense k64 step ----------------
            uint32_t bbase[4];
            #pragma unroll
            for (int p = 0; p < 4; p++)
                bbase[p] = Bs_u + (uint32_t)(wn * 64 + p * 16 + b_col_l) * 128;
            #pragma unroll
            for (int ks = 0; ks < 4; ks++) {
                const uint32_t kb = (uint32_t)(ks * 32);
                uint32_t af[4][4], bf[4][4];
                #pragma unroll
                for (int mi = 0; mi < 4; mi++)
                    ldm_x4(af[mi], abase[mi] + ((kb | a_k16) ^ pat));
                #pragma unroll
                for (int p = 0; p < 4; p++)
                    ldm_x4(bf[p], bbase[p] + ((kb | b_k16) ^ pat));
                #pragma unroll
                for (int mi = 0; mi < 4; mi++)
                    #pragma unroll
                    for (int ni = 0; ni < 8; ni++)
                        mma_f16(acc[mi][ni][0], acc[mi][ni][1],
                                acc[mi][ni][2], acc[mi][ni][3],
                                af[mi][0], af[mi][1], af[mi][2], af[mi][3],
                                bf[ni >> 1][(ni & 1) * 2],
                                bf[ni >> 1][(ni & 1) * 2 + 1]);
            }
        } else {
            // ---------------- sparse superstep (orig k128) ----------------
            #pragma unroll
            for (int j = 0; j < 4; j++) {
                uint32_t af[4][4];
                #pragma unroll
                for (int mi = 0; mi < 4; mi++)
                    ldm_x4(af[mi], abase[mi] + (((uint32_t)(j * 32) | a_k16) ^ pat));
                const uint32_t bchunk = Bs_u + (uint32_t)(j >> 1) * B_CH_BYTES;
                const uint32_t kb_lo = (uint32_t)((j & 1) * 64);
                uint32_t bl[4][4], bh[4][4];
                #pragma unroll
                for (int p = 0; p < 4; p++) {
                    const uint32_t bb =
                        bchunk + (uint32_t)(wn * 64 + p * 16 + b_col_l) * 128;
                    ldm_x4(bl[p], bb + ((kb_lo | b_k16) ^ pat));
                    ldm_x4(bh[p], bb + (((kb_lo + 32) | b_k16) ^ pat));
                }
                #pragma unroll
                for (int mi = 0; mi < 4; mi++)
                    #pragma unroll
                    for (int ni = 0; ni < 8; ni++)
                        mma_sp(acc[mi][ni][0], acc[mi][ni][1],
                               acc[mi][ni][2], acc[mi][ni][3],
                               af[mi][0], af[mi][1], af[mi][2], af[mi][3],
                               bl[ni >> 1][(ni & 1) * 2],
                               bl[ni >> 1][(ni & 1) * 2 + 1],
                               bh[ni >> 1][(ni & 1) * 2],
                               bh[ni >> 1][(ni & 1) * 2 + 1],
                               e[j][mi]);
            }
        }

        if (lane == 0) mbar_arrive(mb_empty + 8 * cs);
        if (++cs == STAGES) { cs = 0; cph ^= 1; }
    }

    // ------ epilogue: partial sums to g_part[kt] ------
    float* part = g_part + (size_t)kt * B_DIM * O_DIM;
    const int l4 = lane >> 2;
    const int lk = lane & 3;
    const int row0 = mt * 256 + wm * 64 + l4;
    const int col0 = nt * 128 + wn * 64 + 2 * lk;
    #pragma unroll
    for (int mi = 0; mi < 4; mi++) {
        #pragma unroll
        for (int ni = 0; ni < 8; ni++) {
            float* p0 = part + (size_t)(row0 + mi * 16)     * O_DIM + col0 + ni * 8;
            float* p1 = part + (size_t)(row0 + mi * 16 + 8) * O_DIM + col0 + ni * 8;
            *reinterpret_cast<float2*>(p0) =
                make_float2(acc[mi][ni][0], acc[mi][ni][1]);
            *reinterpret_cast<float2*>(p1) =
                make_float2(acc[mi][ni][2], acc[mi][ni][3]);
        }
    }
}

// ----------------------------------------------------------- add kernel ----
__global__ void add_out(float* __restrict__ out) {
    const int idx = blockIdx.x * blockDim.x + threadIdx.x;   // float4 index
    const float4 a = reinterpret_cast<const float4*>(g_part)[idx];
    const float4 b = reinterpret_cast<const float4*>(
        g_part + (size_t)B_DIM * O_DIM)[idx];
    float4 r;
    r.x = a.x + b.x; r.y = a.y + b.y; r.z = a.z + b.z; r.w = a.w + b.w;
    reinterpret_cast<float4*>(out)[idx] = r;
}

// ---------------------------------------------------------------- launch ---
extern "C" void kernel_launch(void* const* d_in, const int* in_sizes, int n_in,
                              void* d_out, int out_size) {
    (void)in_sizes; (void)n_in; (void)out_size;
    const float* x = (const float*)d_in[0];   // (2048, 1024) fp32
    const float* w = (const float*)d_in[1];   // (1024, 1024) fp32
    const float* c = (const float*)d_in[2];   // (1024, 1024, 8) fp32
    float* out = (float*)d_out;               // (2048, 1024) fp32

    cudaFuncSetAttribute(kan_gemm,
                         cudaFuncAttributeMaxDynamicSharedMemorySize, SMEM_TOTAL);
    cudaFuncSetAttribute(build_meta,
                         cudaFuncAttributeMaxDynamicSharedMemorySize, 65536);

    build_B<<<dim3(9, O_DIM), 128>>>(w, c);
    build_A<<<(B_DIM * I_DIM + 255) / 256, 256>>>(x);
    build_meta<<<128, 256, 65536>>>(x);
    kan_gemm<<<dim3(MT, NT, KSPLIT), 256, SMEM_TOTAL>>>();
    add_out<<<(B_DIM * O_DIM / 4) / 256, 256>>>(out);
}

// round 16
// speedup vs baseline: 1.1263x; 1.1263x over previous
#include <cuda_runtime.h>
#include <cuda_fp16.h>
#include <cstdint>
#include <cstddef>

// ============================================================================
// KAN layer == fp16 GEMM with 2:4 SPARSE spline block:
//   out[2048,1024] = A[2048,9216] @ Bm[1024,9216]^T
//   A = [ h(x) dense | one-hot(bin)*w -> 2:4 sparse, mma.sp::ordered_metadata ]
//   Bm = [ h(W) | h(0.1*coeff) ]
// R15: GEMM identical to R13 (best measured: 2 CTAs/SM, 128x64 CTA tile,
// 8 warps 4m x 2n, 3-stage pipeline). build_meta FUSED into build_A via
// per-(b,i) byte stores — one fewer kernel, one fewer full X read.
// ============================================================================

namespace {
constexpr int B_DIM  = 2048;
constexpr int I_DIM  = 1024;
constexpr int O_DIM  = 1024;
constexpr int MT     = 16;                 // 2048 / 128
constexpr int NT2    = 16;                 // 1024 / 64
constexpr int STAGES = 3;
constexpr int NSTEP  = 80;                 // 16 dense + 64 sparse supersteps
constexpr int NWARP  = 8;
constexpr int A_CH_HALVES = 128 * 64;      // A chunk: 128 rows x 64 fp16 = 16KB
constexpr int A_CH_BYTES  = A_CH_HALVES * 2;
constexpr int B_CH_HALVES = 64 * 64;       // B chunk: 64 rows x 64 fp16 = 8KB
constexpr int B_CH_BYTES  = B_CH_HALVES * 2;
constexpr int A_CHUNKS    = 80;            // 16 base + 64 compressed spline
constexpr int B_CHUNKS    = 144;           // 16 base + 128 dense spline
constexpr int STAGE_BYTES = A_CH_BYTES + 2 * B_CH_BYTES;   // 32KB
constexpr int SMEM_TOTAL  = 2048 + STAGES * STAGE_BYTES;   // 100352
}  // namespace

// Scratch (__device__ globals; no cudaMalloc allowed).
__device__ __half   g_A   [(size_t)MT * A_CHUNKS * A_CH_HALVES];   // 21 MB
__device__ __half   g_Bm  [(size_t)NT2 * B_CHUNKS * B_CH_HALVES];  // 18.9 MB
// metadata: [global 16-row slab 0..127][k32g 0..255][lane-entry 0..15]
__device__ uint32_t g_meta[(size_t)128 * 256 * 16];                // 2 MB

// ---------------------------------------------------------------- helpers --
__device__ __forceinline__ uint32_t smem_u32(const void* p) {
    uint32_t a;
    asm("{ .reg .u64 t; cvta.to.shared.u64 t, %1; cvt.u32.u64 %0, t; }"
        : "=r"(a) : "l"(p));
    return a;
}
__device__ __forceinline__ uint32_t sw128(uint32_t off) {   // Swizzle<3,4,3>
    return off ^ ((off >> 3) & 0x70);
}
__device__ __forceinline__ void mbar_init(uint32_t m, uint32_t cnt) {
    asm volatile("mbarrier.init.shared.b64 [%0], %1;" :: "r"(m), "r"(cnt) : "memory");
}
__device__ __forceinline__ void mbar_expect_tx(uint32_t m, uint32_t bytes) {
    asm volatile("mbarrier.arrive.expect_tx.shared.b64 _, [%0], %1;"
                 :: "r"(m), "r"(bytes) : "memory");
}
__device__ __forceinline__ void mbar_arrive(uint32_t m) {
    asm volatile("mbarrier.arrive.shared.b64 _, [%0];" :: "r"(m) : "memory");
}
__device__ __forceinline__ void mbar_wait(uint32_t m, uint32_t parity) {
    asm volatile(
        "{\n\t.reg .pred P;\n\t"
        "W%=:\n\t"
        "mbarrier.try_wait.parity.acquire.cta.shared::cta.b64 P, [%0], %1, 0x989680;\n\t"
        "@P bra.uni D%=;\n\t"
        "bra.uni W%=;\n\t"
        "D%=:\n\t}"
        :: "r"(m), "r"(parity) : "memory");
}
__device__ __forceinline__ void mbar_wait_relaxed(uint32_t m, uint32_t parity) {
    asm volatile(
        "{\n\t.reg .pred P;\n\t"
        "W%=:\n\t"
        "mbarrier.try_wait.parity.relaxed.cta.shared::cta.b64 P, [%0], %1, 0x989680;\n\t"
        "@P bra.uni D%=;\n\t"
        "bra.uni W%=;\n\t"
        "D%=:\n\t}"
        :: "r"(m), "r"(parity) : "memory");
}
__device__ __forceinline__ void bulk_g2s(uint32_t dst, const void* src,
                                         uint32_t bytes, uint32_t mbar) {
    asm volatile(
        "cp.async.bulk.shared::cluster.global.mbarrier::complete_tx::bytes "
        "[%0], [%1], %2, [%3];"
        :: "r"(dst), "l"(src), "r"(bytes), "r"(mbar) : "memory");
}
__device__ __forceinline__ void mma_f16(float& c0, float& c1, float& c2, float& c3,
                                        uint32_t a0, uint32_t a1, uint32_t a2,
                                        uint32_t a3, uint32_t b0, uint32_t b1) {
    asm volatile(
        "mma.sync.aligned.m16n8k16.row.col.f32.f16.f16.f32 "
        "{%0,%1,%2,%3}, {%4,%5,%6,%7}, {%8,%9}, {%0,%1,%2,%3};"
        : "+f"(c0), "+f"(c1), "+f"(c2), "+f"(c3)
        : "r"(a0), "r"(a1), "r"(a2), "r"(a3), "r"(b0), "r"(b1));
}
__device__ __forceinline__ void mma_sp(float& c0, float& c1, float& c2, float& c3,
                                       uint32_t a0, uint32_t a1, uint32_t a2,
                                       uint32_t a3, uint32_t b0, uint32_t b1,
                                       uint32_t b2, uint32_t b3, uint32_t e) {
    asm volatile(
        "mma.sp::ordered_metadata.sync.aligned.m16n8k32.row.col.f32.f16.f16.f32 "
        "{%0,%1,%2,%3}, {%4,%5,%6,%7}, {%8,%9,%10,%11}, {%0,%1,%2,%3}, %12, 0x0;"
        : "+f"(c0), "+f"(c1), "+f"(c2), "+f"(c3)
        : "r"(a0), "r"(a1), "r"(a2), "r"(a3),
          "r"(b0), "r"(b1), "r"(b2), "r"(b3), "r"(e));
}
__device__ __forceinline__ void ldm_x4(uint32_t* r, uint32_t addr) {
    asm volatile(
        "ldmatrix.sync.aligned.m8n8.x4.shared.b16 {%0,%1,%2,%3}, [%4];"
        : "=r"(r[0]), "=r"(r[1]), "=r"(r[2]), "=r"(r[3]) : "r"(addr));
}
__device__ __forceinline__ uint32_t h2u(__half2 h) {
    return *reinterpret_cast<uint32_t*>(&h);
}
// reference bucketize: grid knots exact 0.25 multiples; bin clamps to 7
__device__ __forceinline__ int bin_of(float x, float& w) {
    const float xc = fminf(1.0f, fmaxf(-1.0f, x));
    const int gi = (xc >= -0.75f) + (xc >= -0.5f) + (xc >= -0.25f) + (xc >= 0.0f) +
                   (xc >=  0.25f) + (xc >=  0.5f) + (xc >=  0.75f);
    w = (xc - (-1.0f + 0.25f * (float)gi)) * 4.0f;
    return gi;
}

// ------------------------------------------------------------ B builder ----
// 64-row n-tiles: [o>>6][k-chunk][sw128((o&63)*128 + group*16)]
__global__ void build_B(const float* __restrict__ W, const float* __restrict__ C) {
    const int o  = blockIdx.y;
    const int kg = blockIdx.x * 128 + threadIdx.x;   // 0..1151 (8-half groups)
    float4 v0, v1;
    if (blockIdx.x == 0) {
        const float4* p = reinterpret_cast<const float4*>(W + (size_t)o * I_DIM + kg * 8);
        v0 = p[0]; v1 = p[1];
    } else {
        const float4* p = reinterpret_cast<const float4*>(C + (size_t)o * 8192 + (kg * 8 - 1024));
        v0 = p[0]; v1 = p[1];
        v0.x *= 0.1f; v0.y *= 0.1f; v0.z *= 0.1f; v0.w *= 0.1f;
        v1.x *= 0.1f; v1.y *= 0.1f; v1.z *= 0.1f; v1.w *= 0.1f;
    }
    uint4 u;
    u.x = h2u(__floats2half2_rn(v0.x, v0.y));
    u.y = h2u(__floats2half2_rn(v0.z, v0.w));
    u.z = h2u(__floats2half2_rn(v1.x, v1.y));
    u.w = h2u(__floats2half2_rn(v1.z, v1.w));
    const int ntile = o >> 6, r = o & 63, ch = kg >> 3;
    char* cb = (char*)(g_Bm + ((size_t)ntile * B_CHUNKS + ch) * B_CH_HALVES);
    *reinterpret_cast<uint4*>(cb + sw128((uint32_t)(r * 128 + (kg & 7) * 16))) = u;
}

// --------------------------------------- A builder (metadata FUSED in) -----
// Per (b,i): base half, compressed-spline uint2, and ONE metadata byte.
// Metadata word = [slab b>>4][k32g i>>2][entry q*2+t], 4 bytes from 4 (b,i):
//   byte = (i&1) + 2*((b&15) >= 8);  q = b&7;  t = (i>>1)&1.
__global__ void build_A(const float* __restrict__ X) {
    const int idx = blockIdx.x * blockDim.x + threadIdx.x;
    if (idx >= B_DIM * I_DIM) return;
    const int b = idx >> 10, i = idx & 1023;
    const float x = X[idx];
    const int mtile = b >> 7, r = b & 127;
    char* tb = (char*)(g_A + (size_t)mtile * A_CHUNKS * A_CH_HALVES);

    {   // base: chunk i>>6, half col i&63
        const int ch = i >> 6;
        const uint32_t off = sw128((uint32_t)(r * 128 + (i & 63) * 2));
        *reinterpret_cast<__half*>(tb + (size_t)ch * A_CH_BYTES + off) =
            __float2half_rn(x);
    }

    float w; const int gi = bin_of(x, w);

    // compressed spline values: kept slot within the 4 compressed halves
    {
        const int slot = (gi >> 2) * 2 + ((gi & 3) == 3 ? 1 : 0);
        const uint32_t w16 = (uint32_t)__half_as_ushort(__float2half_rn(w));
        uint2 u;
        u.x = (slot < 2) ? (w16 << (slot * 16)) : 0u;
        u.y = (slot >= 2) ? (w16 << ((slot - 2) * 16)) : 0u;
        const int ch = 16 + (i >> 4);
        const uint32_t off = sw128((uint32_t)(r * 128 + (i & 15) * 8));
        *reinterpret_cast<uint2*>(tb + (size_t)ch * A_CH_BYTES + off) = u;
    }

    // metadata byte: nibbles for the two 4-groups (kept pair (p,3) or (0,3))
    {
        const int grp = gi >> 2, p = gi & 3;
        const uint8_t n0 = (uint8_t)(0xCu | ((grp == 0 && p < 3) ? (uint32_t)p : 0u));
        const uint8_t n1 = (uint8_t)(0xCu | ((grp == 1 && p < 3) ? (uint32_t)p : 0u));
        const uint8_t mb = (uint8_t)(n0 | (n1 << 4));
        const int slab = b >> 4, rr = b & 15;
        const int q = rr & 7, up = rr >> 3;
        const int k32g = i >> 2, t = (i >> 1) & 1;
        const size_t word = (size_t)slab * 4096 + (size_t)k32g * 16 + q * 2 + t;
        reinterpret_cast<uint8_t*>(g_meta)[word * 4 + (i & 1) + 2 * up] = mb;
    }
}

// ---------------------------------------------------------------- GEMM -----
// grid (16,16): mt, nt64. 256 threads = 8 warps as 4(m) x 2(n); warp tile
// 32m x 32n. tid0 produces via cp.async.bulk. 3-stage cursor pipeline.
// (identical to R13 — best measured GEMM: 99.5us)
__global__ void __launch_bounds__(256, 2) kan_gemm(float* __restrict__ out) {
    extern __shared__ char smem[];
    const uint32_t sbase = smem_u32(smem);
    const uint32_t hdr   = sbase;
    const uint32_t tiles = (sbase + 2047u) & ~1023u;
    const uint32_t mb_full  = hdr;           // 3 x 8B
    const uint32_t mb_empty = hdr + 64;      // 3 x 8B

    const int tid  = threadIdx.x;
    const int wid  = tid >> 5;
    const int lane = tid & 31;
    const int wm = wid & 3;                  // m-slab 0..3 (32 rows each)
    const int wn = wid >> 2;                 // n-slab 0..1 (32 cols each)
    const int mt = blockIdx.x, nt = blockIdx.y;

    if (tid == 0) {
        #pragma unroll
        for (int s = 0; s < STAGES; s++) {
            mbar_init(mb_full  + 8 * s, 1);
            mbar_init(mb_empty + 8 * s, NWARP);
        }
    }
    __syncthreads();

    const __half* gA = g_A  + (size_t)mt * A_CHUNKS * A_CH_HALVES;
    const __half* gB = g_Bm + (size_t)nt * B_CHUNKS * B_CH_HALVES;

    auto produce = [&](int cc, int ps) {
        const uint32_t dst = tiles + (uint32_t)ps * STAGE_BYTES;
        if (cc < 16) {
            mbar_expect_tx(mb_full + 8 * ps, A_CH_BYTES + B_CH_BYTES);
            bulk_g2s(dst, gA + (size_t)cc * A_CH_HALVES,
                     A_CH_BYTES, mb_full + 8 * ps);
            bulk_g2s(dst + A_CH_BYTES, gB + (size_t)cc * B_CH_HALVES,
                     B_CH_BYTES, mb_full + 8 * ps);
        } else {
            mbar_expect_tx(mb_full + 8 * ps, A_CH_BYTES + 2 * B_CH_BYTES);
            bulk_g2s(dst, gA + (size_t)cc * A_CH_HALVES,
                     A_CH_BYTES, mb_full + 8 * ps);
            bulk_g2s(dst + A_CH_BYTES,
                     gB + (size_t)(2 * cc - 16) * B_CH_HALVES,
                     2 * B_CH_BYTES, mb_full + 8 * ps);
        }
    };

    if (tid == 0) {
        #pragma unroll
        for (int cc = 0; cc < STAGES - 1; cc++) produce(cc, cc);
    }
    int pcc = STAGES - 1, ps = STAGES - 1, pr = 0;

    float acc[2][4][4];                      // [mi][ni][frag]
    #pragma unroll
    for (int mi = 0; mi < 2; mi++)
        #pragma unroll
        for (int ni = 0; ni < 4; ni++)
            #pragma unroll
            for (int q = 0; q < 4; q++) acc[mi][ni][q] = 0.0f;

    // ldmatrix geometry (SW128, row fixed per lane)
    const uint32_t pat   = (uint32_t)(lane & 7) << 4;
    const uint32_t a_k16 = (uint32_t)((lane >> 4) & 1) << 4;
    const uint32_t b_k16 = (uint32_t)((lane >> 3) & 1) << 4;
    const int a_row_l = ((lane >> 3) & 1) * 8 + (lane & 7);
    const int b_col_l = ((lane >> 4) & 1) * 8 + (lane & 7);
    const uint32_t mlane = (uint32_t)(((lane >> 2) << 1) | (lane & 1));
    const size_t meta_base = ((size_t)(mt * 8 + wm * 2)) * 4096;   // +mi*4096

    int cs = 0, cph = 0;                     // consumer cursor

    for (int n = 0; n < NSTEP; n++) {
        if (tid == 0 && pcc < NSTEP) {
            if (pr > 0) mbar_wait_relaxed(mb_empty + 8 * ps, (pr - 1) & 1);
            produce(pcc, ps);
            pcc++;
            if (++ps == STAGES) { ps = 0; pr++; }
        }

        // metadata prefetch before the stage wait (stage-independent GMEM)
        uint32_t e[4][2];
        if (n >= 16) {
            const int m = n - 16;
            #pragma unroll
            for (int j = 0; j < 4; j++)
                #pragma unroll
                for (int mi = 0; mi < 2; mi++)
                    e[j][mi] = g_meta[meta_base + (size_t)mi * 4096 +
                                      (size_t)(m * 4 + j) * 16 + mlane];
        }

        mbar_wait(mb_full + 8 * cs, cph);

        const uint32_t As_u = tiles + (uint32_t)cs * STAGE_BYTES;
        const uint32_t Bs_u = As_u + A_CH_BYTES;

        uint32_t abase[2];
        #pragma unroll
        for (int mi = 0; mi < 2; mi++)
            abase[mi] = As_u + (uint32_t)(wm * 32 + mi * 16 + a_row_l) * 128;

        if (n < 16) {
            // ---------------- dense k64 step ----------------
            uint32_t bbase[2];
            #pragma unroll
            for (int p = 0; p < 2; p++)
                bbase[p] = Bs_u + (uint32_t)(wn * 32 + p * 16 + b_col_l) * 128;
            #pragma unroll
            for (int ks = 0; ks < 4; ks++) {
                const uint32_t kb = (uint32_t)(ks * 32);
                uint32_t af[2][4], bf[2][4];
                #pragma unroll
                for (int mi = 0; mi < 2; mi++)
                    ldm_x4(af[mi], abase[mi] + ((kb | a_k16) ^ pat));
                #pragma unroll
                for (int p = 0; p < 2; p++)
                    ldm_x4(bf[p], bbase[p] + ((kb | b_k16) ^ pat));
                #pragma unroll
                for (int mi = 0; mi < 2; mi++)
                    #pragma unroll
                    for (int ni = 0; ni < 4; ni++)
                        mma_f16(acc[mi][ni][0], acc[mi][ni][1],
                                acc[mi][ni][2], acc[mi][ni][3],
                                af[mi][0], af[mi][1], af[mi][2], af[mi][3],
                                bf[ni >> 1][(ni & 1) * 2],
                                bf[ni >> 1][(ni & 1) * 2 + 1]);
            }
        } else {
            // ---------------- sparse superstep (orig k128) ----------------
            #pragma unroll
            for (int j = 0; j < 4; j++) {
                uint32_t af[2][4];
                #pragma unroll
                for (int mi = 0; mi < 2; mi++)
                    ldm_x4(af[mi], abase[mi] + (((uint32_t)(j * 32) | a_k16) ^ pat));
                const uint32_t bchunk = Bs_u + (uint32_t)(j >> 1) * B_CH_BYTES;
                const uint32_t kb_lo = (uint32_t)((j & 1) * 64);
                uint32_t bl[2][4], bh[2][4];
                #pragma unroll
                for (int p = 0; p < 2; p++) {
                    const uint32_t bb =
                        bchunk + (uint32_t)(wn * 32 + p * 16 + b_col_l) * 128;
                    ldm_x4(bl[p], bb + ((kb_lo | b_k16) ^ pat));
                    ldm_x4(bh[p], bb + (((kb_lo + 32) | b_k16) ^ pat));
                }
                #pragma unroll
                for (int mi = 0; mi < 2; mi++)
                    #pragma unroll
                    for (int ni = 0; ni < 4; ni++)
                        mma_sp(acc[mi][ni][0], acc[mi][ni][1],
                               acc[mi][ni][2], acc[mi][ni][3],
                               af[mi][0], af[mi][1], af[mi][2], af[mi][3],
                               bl[ni >> 1][(ni & 1) * 2],
                               bl[ni >> 1][(ni & 1) * 2 + 1],
                               bh[ni >> 1][(ni & 1) * 2],
                               bh[ni >> 1][(ni & 1) * 2 + 1],
                               e[j][mi]);
            }
        }

        if (lane == 0) mbar_arrive(mb_empty + 8 * cs);
        if (++cs == STAGES) { cs = 0; cph ^= 1; }
    }

    // ------ epilogue ------
    const int l4 = lane >> 2;
    const int lk = lane & 3;
    const int row0 = mt * 128 + wm * 32 + l4;
    const int col0 = nt * 64 + wn * 32 + 2 * lk;
    #pragma unroll
    for (int mi = 0; mi < 2; mi++) {
        #pragma unroll
        for (int ni = 0; ni < 4; ni++) {
            float* p0 = out + (size_t)(row0 + mi * 16)     * O_DIM + col0 + ni * 8;
            float* p1 = out + (size_t)(row0 + mi * 16 + 8) * O_DIM + col0 + ni * 8;
            *reinterpret_cast<float2*>(p0) =
                make_float2(acc[mi][ni][0], acc[mi][ni][1]);
            *reinterpret_cast<float2*>(p1) =
                make_float2(acc[mi][ni][2], acc[mi][ni][3]);
        }
    }
}

// ---------------------------------------------------------------- launch ---
extern "C" void kernel_launch(void* const* d_in, const int* in_sizes, int n_in,
                              void* d_out, int out_size) {
    (void)in_sizes; (void)n_in; (void)out_size;
    const float* x = (const float*)d_in[0];   // (2048, 1024) fp32
    const float* w = (const float*)d_in[1];   // (1024, 1024) fp32
    const float* c = (const float*)d_in[2];   // (1024, 1024, 8) fp32
    float* out = (float*)d_out;               // (2048, 1024) fp32

    cudaFuncSetAttribute(kan_gemm,
                         cudaFuncAttributeMaxDynamicSharedMemorySize, SMEM_TOTAL);

    build_B<<<dim3(9, O_DIM), 128>>>(w, c);
    build_A<<<(B_DIM * I_DIM + 255) / 256, 256>>>(x);
    kan_gemm<<<dim3(MT, NT2), 256, SMEM_TOTAL>>>(out);
}

// round 17
// speedup vs baseline: 1.2112x; 1.0754x over previous
#include <cuda_runtime.h>
#include <cuda_fp16.h>
#include <cstdint>
#include <cstddef>

// ============================================================================
// KAN layer == fp16 GEMM with 2:4 SPARSE spline block:
//   out[2048,1024] = A[2048,9216] @ Bm[1024,9216]^T
//   A = [ h(x) dense | one-hot(bin)*w -> 2:4 sparse, mma.sp::ordered_metadata ]
//   Bm = [ h(W) | h(0.1*coeff) ]
// R16: (a) build_B + build_A fused into ONE kernel (A-blocks fill SM bubbles
// behind B's DRAM traffic; one fewer launch gap); (b) rotating producer in
// the GEMM (chunk cc produced by warp cc&7 — removes the warp-0 convoy).
// GEMM core identical to R13/R15 (best measured: 99.5us).
// ============================================================================

namespace {
constexpr int B_DIM  = 2048;
constexpr int I_DIM  = 1024;
constexpr int O_DIM  = 1024;
constexpr int MT     = 16;                 // 2048 / 128
constexpr int NT2    = 16;                 // 1024 / 64
constexpr int STAGES = 3;
constexpr int NSTEP  = 80;                 // 16 dense + 64 sparse supersteps
constexpr int NWARP  = 8;
constexpr int A_CH_HALVES = 128 * 64;      // A chunk: 128 rows x 64 fp16 = 16KB
constexpr int A_CH_BYTES  = A_CH_HALVES * 2;
constexpr int B_CH_HALVES = 64 * 64;       // B chunk: 64 rows x 64 fp16 = 8KB
constexpr int B_CH_BYTES  = B_CH_HALVES * 2;
constexpr int A_CHUNKS    = 80;            // 16 base + 64 compressed spline
constexpr int B_CHUNKS    = 144;           // 16 base + 128 dense spline
constexpr int STAGE_BYTES = A_CH_BYTES + 2 * B_CH_BYTES;   // 32KB
constexpr int SMEM_TOTAL  = 2048 + STAGES * STAGE_BYTES;   // 100352
constexpr int NBLK_B = 9 * O_DIM;          // 9216 builder blocks for B
constexpr int NBLK_A = (B_DIM * I_DIM) / 128;  // 16384 builder blocks for A
}  // namespace

// Scratch (__device__ globals; no cudaMalloc allowed).
__device__ __half   g_A   [(size_t)MT * A_CHUNKS * A_CH_HALVES];   // 21 MB
__device__ __half   g_Bm  [(size_t)NT2 * B_CHUNKS * B_CH_HALVES];  // 18.9 MB
// metadata: [global 16-row slab 0..127][k32g 0..255][lane-entry 0..15]
__device__ uint32_t g_meta[(size_t)128 * 256 * 16];                // 2 MB

// ---------------------------------------------------------------- helpers --
__device__ __forceinline__ uint32_t smem_u32(const void* p) {
    uint32_t a;
    asm("{ .reg .u64 t; cvta.to.shared.u64 t, %1; cvt.u32.u64 %0, t; }"
        : "=r"(a) : "l"(p));
    return a;
}
__device__ __forceinline__ uint32_t sw128(uint32_t off) {   // Swizzle<3,4,3>
    return off ^ ((off >> 3) & 0x70);
}
__device__ __forceinline__ void mbar_init(uint32_t m, uint32_t cnt) {
    asm volatile("mbarrier.init.shared.b64 [%0], %1;" :: "r"(m), "r"(cnt) : "memory");
}
__device__ __forceinline__ void mbar_expect_tx(uint32_t m, uint32_t bytes) {
    asm volatile("mbarrier.arrive.expect_tx.shared.b64 _, [%0], %1;"
                 :: "r"(m), "r"(bytes) : "memory");
}
__device__ __forceinline__ void mbar_arrive(uint32_t m) {
    asm volatile("mbarrier.arrive.shared.b64 _, [%0];" :: "r"(m) : "memory");
}
__device__ __forceinline__ void mbar_wait(uint32_t m, uint32_t parity) {
    asm volatile(
        "{\n\t.reg .pred P;\n\t"
        "W%=:\n\t"
        "mbarrier.try_wait.parity.acquire.cta.shared::cta.b64 P, [%0], %1, 0x989680;\n\t"
        "@P bra.uni D%=;\n\t"
        "bra.uni W%=;\n\t"
        "D%=:\n\t}"
        :: "r"(m), "r"(parity) : "memory");
}
__device__ __forceinline__ void mbar_wait_relaxed(uint32_t m, uint32_t parity) {
    asm volatile(
        "{\n\t.reg .pred P;\n\t"
        "W%=:\n\t"
        "mbarrier.try_wait.parity.relaxed.cta.shared::cta.b64 P, [%0], %1, 0x989680;\n\t"
        "@P bra.uni D%=;\n\t"
        "bra.uni W%=;\n\t"
        "D%=:\n\t}"
        :: "r"(m), "r"(parity) : "memory");
}
__device__ __forceinline__ void bulk_g2s(uint32_t dst, const void* src,
                                         uint32_t bytes, uint32_t mbar) {
    asm volatile(
        "cp.async.bulk.shared::cluster.global.mbarrier::complete_tx::bytes "
        "[%0], [%1], %2, [%3];"
        :: "r"(dst), "l"(src), "r"(bytes), "r"(mbar) : "memory");
}
__device__ __forceinline__ void mma_f16(float& c0, float& c1, float& c2, float& c3,
                                        uint32_t a0, uint32_t a1, uint32_t a2,
                                        uint32_t a3, uint32_t b0, uint32_t b1) {
    asm volatile(
        "mma.sync.aligned.m16n8k16.row.col.f32.f16.f16.f32 "
        "{%0,%1,%2,%3}, {%4,%5,%6,%7}, {%8,%9}, {%0,%1,%2,%3};"
        : "+f"(c0), "+f"(c1), "+f"(c2), "+f"(c3)
        : "r"(a0), "r"(a1), "r"(a2), "r"(a3), "r"(b0), "r"(b1));
}
__device__ __forceinline__ void mma_sp(float& c0, float& c1, float& c2, float& c3,
                                       uint32_t a0, uint32_t a1, uint32_t a2,
                                       uint32_t a3, uint32_t b0, uint32_t b1,
                                       uint32_t b2, uint32_t b3, uint32_t e) {
    asm volatile(
        "mma.sp::ordered_metadata.sync.aligned.m16n8k32.row.col.f32.f16.f16.f32 "
        "{%0,%1,%2,%3}, {%4,%5,%6,%7}, {%8,%9,%10,%11}, {%0,%1,%2,%3}, %12, 0x0;"
        : "+f"(c0), "+f"(c1), "+f"(c2), "+f"(c3)
        : "r"(a0), "r"(a1), "r"(a2), "r"(a3),
          "r"(b0), "r"(b1), "r"(b2), "r"(b3), "r"(e));
}
__device__ __forceinline__ void ldm_x4(uint32_t* r, uint32_t addr) {
    asm volatile(
        "ldmatrix.sync.aligned.m8n8.x4.shared.b16 {%0,%1,%2,%3}, [%4];"
        : "=r"(r[0]), "=r"(r[1]), "=r"(r[2]), "=r"(r[3]) : "r"(addr));
}
__device__ __forceinline__ uint32_t h2u(__half2 h) {
    return *reinterpret_cast<uint32_t*>(&h);
}
// reference bucketize: grid knots exact 0.25 multiples; bin clamps to 7
__device__ __forceinline__ int bin_of(float x, float& w) {
    const float xc = fminf(1.0f, fmaxf(-1.0f, x));
    const int gi = (xc >= -0.75f) + (xc >= -0.5f) + (xc >= -0.25f) + (xc >= 0.0f) +
                   (xc >=  0.25f) + (xc >=  0.5f) + (xc >=  0.75f);
    w = (xc - (-1.0f + 0.25f * (float)gi)) * 4.0f;
    return gi;
}

// ----------------------------------------------- fused A+B+meta builder ----
// blocks [0, NBLK_B): Bm tiles.  blocks [NBLK_B, NBLK_B+NBLK_A): A + meta.
__global__ void build_AB(const float* __restrict__ X,
                         const float* __restrict__ W,
                         const float* __restrict__ C) {
    const int blk = blockIdx.x;
    const int tid = threadIdx.x;

    if (blk < NBLK_B) {
        // ---------------- B part: 64-row n-tiles, SW128-swizzled ----------
        const int o  = blk & 1023;           // output feature
        const int xp = blk >> 10;            // 0..8
        const int kg = xp * 128 + tid;       // 8-half group 0..1151
        float4 v0, v1;
        if (xp == 0) {
            const float4* p = reinterpret_cast<const float4*>(
                W + (size_t)o * I_DIM + kg * 8);
            v0 = p[0]; v1 = p[1];
        } else {
            const float4* p = reinterpret_cast<const float4*>(
                C + (size_t)o * 8192 + (kg * 8 - 1024));
            v0 = p[0]; v1 = p[1];
            v0.x *= 0.1f; v0.y *= 0.1f; v0.z *= 0.1f; v0.w *= 0.1f;
            v1.x *= 0.1f; v1.y *= 0.1f; v1.z *= 0.1f; v1.w *= 0.1f;
        }
        uint4 u;
        u.x = h2u(__floats2half2_rn(v0.x, v0.y));
        u.y = h2u(__floats2half2_rn(v0.z, v0.w));
        u.z = h2u(__floats2half2_rn(v1.x, v1.y));
        u.w = h2u(__floats2half2_rn(v1.z, v1.w));
        const int ntile = o >> 6, r = o & 63, ch = kg >> 3;
        char* cb = (char*)(g_Bm + ((size_t)ntile * B_CHUNKS + ch) * B_CH_HALVES);
        *reinterpret_cast<uint4*>(
            cb + sw128((uint32_t)(r * 128 + (kg & 7) * 16))) = u;
    } else {
        // ---------------- A part: base + compressed spline + metadata -----
        const int idx = (blk - NBLK_B) * 128 + tid;
        const int b = idx >> 10, i = idx & 1023;
        const float x = X[idx];
        const int mtile = b >> 7, r = b & 127;
        char* tb = (char*)(g_A + (size_t)mtile * A_CHUNKS * A_CH_HALVES);

        {   // base: chunk i>>6, half col i&63
            const int ch = i >> 6;
            const uint32_t off = sw128((uint32_t)(r * 128 + (i & 63) * 2));
            *reinterpret_cast<__half*>(tb + (size_t)ch * A_CH_BYTES + off) =
                __float2half_rn(x);
        }

        float w; const int gi = bin_of(x, w);

        {   // compressed spline values
            const int slot = (gi >> 2) * 2 + ((gi & 3) == 3 ? 1 : 0);
            const uint32_t w16 = (uint32_t)__half_as_ushort(__float2half_rn(w));
            uint2 u;
            u.x = (slot < 2) ? (w16 << (slot * 16)) : 0u;
            u.y = (slot >= 2) ? (w16 << ((slot - 2) * 16)) : 0u;
            const int ch = 16 + (i >> 4);
            const uint32_t off = sw128((uint32_t)(r * 128 + (i & 15) * 8));
            *reinterpret_cast<uint2*>(tb + (size_t)ch * A_CH_BYTES + off) = u;
        }

        {   // metadata byte
            const int grp = gi >> 2, p = gi & 3;
            const uint8_t n0 =
                (uint8_t)(0xCu | ((grp == 0 && p < 3) ? (uint32_t)p : 0u));
            const uint8_t n1 =
                (uint8_t)(0xCu | ((grp == 1 && p < 3) ? (uint32_t)p : 0u));
            const uint8_t mb = (uint8_t)(n0 | (n1 << 4));
            const int slab = b >> 4, rr = b & 15;
            const int q = rr & 7, up = rr >> 3;
            const int k32g = i >> 2, t = (i >> 1) & 1;
            const size_t word =
                (size_t)slab * 4096 + (size_t)k32g * 16 + q * 2 + t;
            reinterpret_cast<uint8_t*>(g_meta)[word * 4 + (i & 1) + 2 * up] = mb;
        }
    }
}

// ---------------------------------------------------------------- GEMM -----
// grid (16,16): mt, nt64. 256 threads = 8 warps as 4(m) x 2(n); warp tile
// 32m x 32n. ROTATING producer: chunk cc produced by warp (cc & 7), lane 0.
__global__ void __launch_bounds__(256, 2) kan_gemm(float* __restrict__ out) {
    extern __shared__ char smem[];
    const uint32_t sbase = smem_u32(smem);
    const uint32_t hdr   = sbase;
    const uint32_t tiles = (sbase + 2047u) & ~1023u;
    const uint32_t mb_full  = hdr;           // 3 x 8B
    const uint32_t mb_empty = hdr + 64;      // 3 x 8B

    const int tid  = threadIdx.x;
    const int wid  = tid >> 5;
    const int lane = tid & 31;
    const int wm = wid & 3;                  // m-slab 0..3 (32 rows each)
    const int wn = wid >> 2;                 // n-slab 0..1 (32 cols each)
    const int mt = blockIdx.x, nt = blockIdx.y;

    if (tid == 0) {
        #pragma unroll
        for (int s = 0; s < STAGES; s++) {
            mbar_init(mb_full  + 8 * s, 1);
            mbar_init(mb_empty + 8 * s, NWARP);
        }
    }
    __syncthreads();

    const __half* gA = g_A  + (size_t)mt * A_CHUNKS * A_CH_HALVES;
    const __half* gB = g_Bm + (size_t)nt * B_CHUNKS * B_CH_HALVES;

    auto produce = [&](int cc, int ps) {
        const uint32_t dst = tiles + (uint32_t)ps * STAGE_BYTES;
        if (cc < 16) {
            mbar_expect_tx(mb_full + 8 * ps, A_CH_BYTES + B_CH_BYTES);
            bulk_g2s(dst, gA + (size_t)cc * A_CH_HALVES,
                     A_CH_BYTES, mb_full + 8 * ps);
            bulk_g2s(dst + A_CH_BYTES, gB + (size_t)cc * B_CH_HALVES,
                     B_CH_BYTES, mb_full + 8 * ps);
        } else {
            mbar_expect_tx(mb_full + 8 * ps, A_CH_BYTES + 2 * B_CH_BYTES);
            bulk_g2s(dst, gA + (size_t)cc * A_CH_HALVES,
                     A_CH_BYTES, mb_full + 8 * ps);
            bulk_g2s(dst + A_CH_BYTES,
                     gB + (size_t)(2 * cc - 16) * B_CH_HALVES,
                     2 * B_CH_BYTES, mb_full + 8 * ps);
        }
    };

    // prologue: chunks 0..STAGES-2 produced by warps 0..STAGES-2 (rotating rule)
    if (lane == 0 && wid < STAGES - 1)
        produce(wid, wid);

    float acc[2][4][4];                      // [mi][ni][frag]
    #pragma unroll
    for (int mi = 0; mi < 2; mi++)
        #pragma unroll
        for (int ni = 0; ni < 4; ni++)
            #pragma unroll
            for (int q = 0; q < 4; q++) acc[mi][ni][q] = 0.0f;

    // ldmatrix geometry (SW128, row fixed per lane)
    const uint32_t pat   = (uint32_t)(lane & 7) << 4;
    const uint32_t a_k16 = (uint32_t)((lane >> 4) & 1) << 4;
    const uint32_t b_k16 = (uint32_t)((lane >> 3) & 1) << 4;
    const int a_row_l = ((lane >> 3) & 1) * 8 + (lane & 7);
    const int b_col_l = ((lane >> 4) & 1) * 8 + (lane & 7);
    const uint32_t mlane = (uint32_t)(((lane >> 2) << 1) | (lane & 1));
    const size_t meta_base = ((size_t)(mt * 8 + wm * 2)) * 4096;   // +mi*4096

    int cs = 0, cph = 0;                     // consumer cursor

    for (int n = 0; n < NSTEP; n++) {
        // rotating producer: chunk cc = n + STAGES-1, by warp (cc & 7)
        {
            const int cc = n + STAGES - 1;
            if (cc < NSTEP && wid == (cc & 7) && lane == 0) {
                const int ps2 = cc % STAGES;
                const int r2  = cc / STAGES;
                if (r2 > 0) mbar_wait_relaxed(mb_empty + 8 * ps2, (r2 - 1) & 1);
                produce(cc, ps2);
            }
        }

        // metadata prefetch before the stage wait (stage-independent GMEM)
        uint32_t e[4][2];
        if (n >= 16) {
            const int m = n - 16;
            #pragma unroll
            for (int j = 0; j < 4; j++)
                #pragma unroll
                for (int mi = 0; mi < 2; mi++)
                    e[j][mi] = g_meta[meta_base + (size_t)mi * 4096 +
                                      (size_t)(m * 4 + j) * 16 + mlane];
        }

        mbar_wait(mb_full + 8 * cs, cph);

        const uint32_t As_u = tiles + (uint32_t)cs * STAGE_BYTES;
        const uint32_t Bs_u = As_u + A_CH_BYTES;

        uint32_t abase[2];
        #pragma unroll
        for (int mi = 0; mi < 2; mi++)
            abase[mi] = As_u + (uint32_t)(wm * 32 + mi * 16 + a_row_l) * 128;

        if (n < 16) {
            // ---------------- dense k64 step ----------------
            uint32_t bbase[2];
            #pragma unroll
            for (int p = 0; p < 2; p++)
                bbase[p] = Bs_u + (uint32_t)(wn * 32 + p * 16 + b_col_l) * 128;
            #pragma unroll
            for (int ks = 0; ks < 4; ks++) {
                const uint32_t kb = (uint32_t)(ks * 32);
                uint32_t af[2][4], bf[2][4];
                #pragma unroll
                for (int mi = 0; mi < 2; mi++)
                    ldm_x4(af[mi], abase[mi] + ((kb | a_k16) ^ pat));
                #pragma unroll
                for (int p = 0; p < 2; p++)
                    ldm_x4(bf[p], bbase[p] + ((kb | b_k16) ^ pat));
                #pragma unroll
                for (int mi = 0; mi < 2; mi++)
                    #pragma unroll
                    for (int ni = 0; ni < 4; ni++)
                        mma_f16(acc[mi][ni][0], acc[mi][ni][1],
                                acc[mi][ni][2], acc[mi][ni][3],
                                af[mi][0], af[mi][1], af[mi][2], af[mi][3],
                                bf[ni >> 1][(ni & 1) * 2],
                                bf[ni >> 1][(ni & 1) * 2 + 1]);
            }
        } else {
            // ---------------- sparse superstep (orig k128) ----------------
            #pragma unroll
            for (int j = 0; j < 4; j++) {
                uint32_t af[2][4];
                #pragma unroll
                for (int mi = 0; mi < 2; mi++)
                    ldm_x4(af[mi], abase[mi] + (((uint32_t)(j * 32) | a_k16) ^ pat));
                const uint32_t bchunk = Bs_u + (uint32_t)(j >> 1) * B_CH_BYTES;
                const uint32_t kb_lo = (uint32_t)((j & 1) * 64);
                uint32_t bl[2][4], bh[2][4];
                #pragma unroll
                for (int p = 0; p < 2; p++) {
                    const uint32_t bb =
                        bchunk + (uint32_t)(wn * 32 + p * 16 + b_col_l) * 128;
                    ldm_x4(bl[p], bb + ((kb_lo | b_k16) ^ pat));
                    ldm_x4(bh[p], bb + (((kb_lo + 32) | b_k16) ^ pat));
                }
                #pragma unroll
                for (int mi = 0; mi < 2; mi++)
                    #pragma unroll
                    for (int ni = 0; ni < 4; ni++)
                        mma_sp(acc[mi][ni][0], acc[mi][ni][1],
                               acc[mi][ni][2], acc[mi][ni][3],
                               af[mi][0], af[mi][1], af[mi][2], af[mi][3],
                               bl[ni >> 1][(ni & 1) * 2],
                               bl[ni >> 1][(ni & 1) * 2 + 1],
                               bh[ni >> 1][(ni & 1) * 2],
                               bh[ni >> 1][(ni & 1) * 2 + 1],
                               e[j][mi]);
            }
        }

        if (lane == 0) mbar_arrive(mb_empty + 8 * cs);
        if (++cs == STAGES) { cs = 0; cph ^= 1; }
    }

    // ------ epilogue ------
    const int l4 = lane >> 2;
    const int lk = lane & 3;
    const int row0 = mt * 128 + wm * 32 + l4;
    const int col0 = nt * 64 + wn * 32 + 2 * lk;
    #pragma unroll
    for (int mi = 0; mi < 2; mi++) {
        #pragma unroll
        for (int ni = 0; ni < 4; ni++) {
            float* p0 = out + (size_t)(row0 + mi * 16)     * O_DIM + col0 + ni * 8;
            float* p1 = out + (size_t)(row0 + mi * 16 + 8) * O_DIM + col0 + ni * 8;
            *reinterpret_cast<float2*>(p0) =
                make_float2(acc[mi][ni][0], acc[mi][ni][1]);
            *reinterpret_cast<float2*>(p1) =
                make_float2(acc[mi][ni][2], acc[mi][ni][3]);
        }
    }
}

// ---------------------------------------------------------------- launch ---
extern "C" void kernel_launch(void* const* d_in, const int* in_sizes, int n_in,
                              void* d_out, int out_size) {
    (void)in_sizes; (void)n_in; (void)out_size;
    const float* x = (const float*)d_in[0];   // (2048, 1024) fp32
    const float* w = (const float*)d_in[1];   // (1024, 1024) fp32
    const float* c = (const float*)d_in[2];   // (1024, 1024, 8) fp32
    float* out = (float*)d_out;               // (2048, 1024) fp32

    cudaFuncSetAttribute(kan_gemm,
                         cudaFuncAttributeMaxDynamicSharedMemorySize, SMEM_TOTAL);

    build_AB<<<NBLK_B + NBLK_A, 128>>>(x, w, c);
    kan_gemm<<<dim3(MT, NT2), 256, SMEM_TOTAL>>>(out);
}